// round 1
// baseline (speedup 1.0000x reference)
#include <cuda_runtime.h>
#include <cuda_bf16.h>
#include <cstdint>

#define S2     4096
#define SDIM   64
#define RF     15
#define NPATCH 225
#define INPUT  48
#define ITERS  50

// ---------------- scratch (device globals: allocation-free) ----------------
__device__ __align__(16) __nv_bfloat16 g_W1[(size_t)S2 * S2];  // l4_w  (lwe - mid_norm)
__device__ __align__(16) __nv_bfloat16 g_W2[(size_t)S2 * S2];  // exc_n - inh_n
__device__ float g_aff[S2];
__device__ float g_cur[2][S2];
__device__ float g_l4[2][S2];
__device__ unsigned g_barcnt = 0;
__device__ volatile unsigned g_bargen = 0;

// ---------------- kernel 1: afferent drive + state init --------------------
// afferent[u] = sum_{i in 225} img[rf[u,i,0], rf[u,i,1]] * w[u,i]
__global__ void aff_init_kernel(const float* __restrict__ img,
                                const int*   __restrict__ rfg,
                                const float* __restrict__ aw) {
    int gtid = blockIdx.x * blockDim.x + threadIdx.x;
    if (gtid < S2) {
        g_cur[0][gtid] = 0.f; g_cur[1][gtid] = 0.f;
        g_l4[0][gtid]  = 0.f; g_l4[1][gtid]  = 0.f;
    }
    int u    = gtid >> 5;
    int lane = gtid & 31;
    if (u >= S2) return;
    const int*   rg = rfg + (size_t)u * NPATCH * 2;
    const float* ww = aw  + (size_t)u * NPATCH;
    float s = 0.f;
    for (int i = lane; i < NPATCH; i += 32) {
        int g0 = rg[2 * i];
        int g1 = rg[2 * i + 1];
        s += img[g0 * INPUT + g1] * ww[i];
    }
    #pragma unroll
    for (int o = 16; o; o >>= 1) s += __shfl_xor_sync(0xFFFFFFFFu, s, o);
    if (lane == 0) g_aff[u] = s;
}

// ---------------- kernel 2: build loop-invariant bf16 matrices -------------
// One block per row. Pass A: row sums. Pass B (L1-resident re-read): write bf16.
__global__ void build_w_kernel(const float* __restrict__ lc,
                               const float* __restrict__ l4c,
                               const float* __restrict__ lwe,
                               const float* __restrict__ masks) {
    const int i = blockIdx.x;
    const size_t rb = (size_t)i * S2;
    const float4* lc4  = reinterpret_cast<const float4*>(lc    + rb);
    const float4* l4c4 = reinterpret_cast<const float4*>(l4c   + rb);
    const float4* mk4  = reinterpret_cast<const float4*>(masks + rb);
    const float4* we4  = reinterpret_cast<const float4*>(lwe   + rb);
    const float C15 = 1.5f / 4096.0f;
    const float C10 = 1.0f / 4096.0f;

    float sm = 0.f, se = 0.f, si = 0.f;
    for (int j = threadIdx.x; j < S2 / 4; j += blockDim.x) {
        float4 a = l4c4[j], m = mk4[j], c = lc4[j];
        sm += a.x * (1.f - m.x) + a.y * (1.f - m.y) + a.z * (1.f - m.z) + a.w * (1.f - m.w);
        se += fmaxf(c.x - C15, 0.f) + fmaxf(c.y - C15, 0.f) + fmaxf(c.z - C15, 0.f) + fmaxf(c.w - C15, 0.f);
        si += fmaxf(c.x - C10, 0.f) + fmaxf(c.y - C10, 0.f) + fmaxf(c.z - C10, 0.f) + fmaxf(c.w - C10, 0.f);
    }
    __shared__ float sred[3][8];
    __shared__ float sinv[3];
    int lane = threadIdx.x & 31, w = threadIdx.x >> 5;
    #pragma unroll
    for (int o = 16; o; o >>= 1) {
        sm += __shfl_xor_sync(0xFFFFFFFFu, sm, o);
        se += __shfl_xor_sync(0xFFFFFFFFu, se, o);
        si += __shfl_xor_sync(0xFFFFFFFFu, si, o);
    }
    if (lane == 0) { sred[0][w] = sm; sred[1][w] = se; sred[2][w] = si; }
    __syncthreads();
    if (threadIdx.x < 3) {
        float t = 0.f;
        for (int k = 0; k < (int)(blockDim.x >> 5); k++) t += sred[threadIdx.x][k];
        sinv[threadIdx.x] = 1.0f / (t + 1e-11f);
    }
    __syncthreads();
    const float im = sinv[0], ie = sinv[1], ii = sinv[2];

    __nv_bfloat162* w1 = reinterpret_cast<__nv_bfloat162*>(g_W1 + rb);
    __nv_bfloat162* w2 = reinterpret_cast<__nv_bfloat162*>(g_W2 + rb);
    for (int j = threadIdx.x; j < S2 / 4; j += blockDim.x) {
        float4 a = l4c4[j], m = mk4[j], c = lc4[j], e = we4[j];
        float o1x = e.x - a.x * (1.f - m.x) * im;
        float o1y = e.y - a.y * (1.f - m.y) * im;
        float o1z = e.z - a.z * (1.f - m.z) * im;
        float o1w = e.w - a.w * (1.f - m.w) * im;
        float o2x = fmaxf(c.x - C15, 0.f) * ie - fmaxf(c.x - C10, 0.f) * ii;
        float o2y = fmaxf(c.y - C15, 0.f) * ie - fmaxf(c.y - C10, 0.f) * ii;
        float o2z = fmaxf(c.z - C15, 0.f) * ie - fmaxf(c.z - C10, 0.f) * ii;
        float o2w = fmaxf(c.w - C15, 0.f) * ie - fmaxf(c.w - C10, 0.f) * ii;
        w1[2 * j]     = __floats2bfloat162_rn(o1x, o1y);
        w1[2 * j + 1] = __floats2bfloat162_rn(o1z, o1w);
        w2[2 * j]     = __floats2bfloat162_rn(o2x, o2y);
        w2[2 * j + 1] = __floats2bfloat162_rn(o2z, o2w);
    }
}

// ---------------- kernel 3: persistent 50-step recurrence ------------------
__device__ __forceinline__ void dot8(float& s, uint4 v, const float* __restrict__ x) {
    float2 f0 = __bfloat1622float2(*reinterpret_cast<const __nv_bfloat162*>(&v.x));
    float2 f1 = __bfloat1622float2(*reinterpret_cast<const __nv_bfloat162*>(&v.y));
    float2 f2 = __bfloat1622float2(*reinterpret_cast<const __nv_bfloat162*>(&v.z));
    float2 f3 = __bfloat1622float2(*reinterpret_cast<const __nv_bfloat162*>(&v.w));
    s = fmaf(f0.x, x[0], s); s = fmaf(f0.y, x[1], s);
    s = fmaf(f1.x, x[2], s); s = fmaf(f1.y, x[3], s);
    s = fmaf(f2.x, x[4], s); s = fmaf(f2.y, x[5], s);
    s = fmaf(f3.x, x[6], s); s = fmaf(f3.y, x[7], s);
}

__global__ void __launch_bounds__(1024, 1)
iterate_kernel(const float* __restrict__ thr,
               const float* __restrict__ l4thr,
               float* __restrict__ out,
               int nb) {
    __shared__ float xs[2 * S2];   // [0..4095]=l4_prev, [4096..]=cur_prev
    const int tid  = threadIdx.x;
    const int w    = tid >> 5;
    const int lane = tid & 31;
    const int G    = gridDim.x;

    for (int it = 0; it < ITERS; ++it) {
        const int src = it & 1;
        const int dst = src ^ 1;
        for (int k = tid; k < S2; k += blockDim.x) {
            xs[k]      = g_l4[src][k];
            xs[S2 + k] = g_cur[src][k];
        }
        __syncthreads();

        for (int r = blockIdx.x + G * w; r < S2; r += G * 32) {
            const uint4* row1 = reinterpret_cast<const uint4*>(g_W1) + (size_t)r * 512;
            const uint4* row2 = reinterpret_cast<const uint4*>(g_W2) + (size_t)r * 512;
            float s1 = 0.f, s2 = 0.f;
            #pragma unroll
            for (int j = 0; j < 16; ++j) {
                const int idx = j * 32 + lane;
                uint4 v1 = row1[idx];
                uint4 v2 = row2[idx];
                dot8(s1, v1, xs + idx * 8);
                dot8(s2, v2, xs + S2 + idx * 8);
            }
            #pragma unroll
            for (int o = 16; o; o >>= 1) {
                s1 += __shfl_xor_sync(0xFFFFFFFFu, s1, o);
                s2 += __shfl_xor_sync(0xFFFFFFFFu, s2, o);
            }
            if (lane == 0) {
                // b*0.5 = (0.5/(0.5+1e-11))*0.5 rounds to 0.5f exactly in fp32
                float l4a  = g_aff[r] * 0.5f + xs[S2 + r] * 0.5f;
                float l4n  = tanhf(fmaxf(l4a + s1 - l4thr[r], 0.f) * 2.0f);
                float curn = tanhf(fmaxf(l4n + s2 - thr[r], 0.f));
                g_l4[dst][r]  = l4n;
                g_cur[dst][r] = curn;
                if (it == ITERS - 1) out[r] = curn;
            }
        }

        // ---- grid barrier (sense-reversing; grid == #SMs so all co-resident)
        __syncthreads();
        if (tid == 0) {
            __threadfence();
            unsigned gen = g_bargen;
            if (atomicAdd(&g_barcnt, 1u) == (unsigned)nb - 1u) {
                g_barcnt = 0;
                __threadfence();
                g_bargen = gen + 1u;
            } else {
                while (g_bargen == gen) { }
            }
            __threadfence();
        }
        __syncthreads();
    }
}

// ---------------------------------------------------------------------------
extern "C" void kernel_launch(void* const* d_in, const int* in_sizes, int n_in,
                              void* d_out, int out_size) {
    const float* input_crop = (const float*)d_in[0];
    const int*   rf_grids   = (const int*)  d_in[1];
    const float* aff_w      = (const float*)d_in[2];
    const float* lc         = (const float*)d_in[3];
    const float* l4c        = (const float*)d_in[4];
    const float* lwe        = (const float*)d_in[5];
    const float* masks      = (const float*)d_in[6];
    const float* thr        = (const float*)d_in[7];
    const float* l4thr      = (const float*)d_in[8];
    float* out = (float*)d_out;

    int sms = 148;
    cudaDeviceGetAttribute(&sms, cudaDevAttrMultiProcessorCount, 0);
    if (sms < 1) sms = 148;

    aff_init_kernel<<<512, 256>>>(input_crop, rf_grids, aff_w);
    build_w_kernel<<<S2, 256>>>(lc, l4c, lwe, masks);
    iterate_kernel<<<sms, 1024>>>(thr, l4thr, out, sms);
}

// round 3
// speedup vs baseline: 5.6175x; 5.6175x over previous
#include <cuda_runtime.h>
#include <cuda_bf16.h>
#include <cstdint>

#define S2     4096
#define RF     15
#define NPATCH 225
#define INPUT  48
#define ITERS  50
#define CHUNK  512                 // columns per pipeline chunk
#define NCHUNK (S2 / CHUNK)        // 8
#define NWSLOT 16                  // max active warps per block (G >= 128)

// ---------------- scratch (device globals: allocation-free) ----------------
__device__ __align__(16) __nv_bfloat16 g_W1[(size_t)S2 * S2];  // l4_w
__device__ __align__(16) __nv_bfloat16 g_W2[(size_t)S2 * S2];  // exc_n - inh_n
__device__ float g_aff[S2];
__device__ float g_cur[2][S2];
__device__ float g_l4[2][S2];
__device__ unsigned g_barcnt = 0;
__device__ volatile unsigned g_bargen = 0;

// ---------------- kernel 1: afferent drive + state init --------------------
__global__ void aff_init_kernel(const float* __restrict__ img,
                                const int*   __restrict__ rfg,
                                const float* __restrict__ aw) {
    int gtid = blockIdx.x * blockDim.x + threadIdx.x;
    if (gtid < S2) {
        g_cur[0][gtid] = 0.f; g_cur[1][gtid] = 0.f;
        g_l4[0][gtid]  = 0.f; g_l4[1][gtid]  = 0.f;
    }
    int u    = gtid >> 5;
    int lane = gtid & 31;
    if (u >= S2) return;
    const int*   rg = rfg + (size_t)u * NPATCH * 2;
    const float* ww = aw  + (size_t)u * NPATCH;
    float s = 0.f;
    for (int i = lane; i < NPATCH; i += 32) {
        int g0 = rg[2 * i];
        int g1 = rg[2 * i + 1];
        s += img[g0 * INPUT + g1] * ww[i];
    }
    #pragma unroll
    for (int o = 16; o; o >>= 1) s += __shfl_xor_sync(0xFFFFFFFFu, s, o);
    if (lane == 0) g_aff[u] = s;
}

// ---------------- kernel 2: build loop-invariant bf16 matrices -------------
__global__ void build_w_kernel(const float* __restrict__ lc,
                               const float* __restrict__ l4c,
                               const float* __restrict__ lwe,
                               const float* __restrict__ masks) {
    const int i = blockIdx.x;
    const size_t rb = (size_t)i * S2;
    const float4* lc4  = reinterpret_cast<const float4*>(lc    + rb);
    const float4* l4c4 = reinterpret_cast<const float4*>(l4c   + rb);
    const float4* mk4  = reinterpret_cast<const float4*>(masks + rb);
    const float4* we4  = reinterpret_cast<const float4*>(lwe   + rb);
    const float C15 = 1.5f / 4096.0f;
    const float C10 = 1.0f / 4096.0f;

    float sm = 0.f, se = 0.f, si = 0.f;
    for (int j = threadIdx.x; j < S2 / 4; j += blockDim.x) {
        float4 a = l4c4[j], m = mk4[j], c = lc4[j];
        sm += a.x * (1.f - m.x) + a.y * (1.f - m.y) + a.z * (1.f - m.z) + a.w * (1.f - m.w);
        se += fmaxf(c.x - C15, 0.f) + fmaxf(c.y - C15, 0.f) + fmaxf(c.z - C15, 0.f) + fmaxf(c.w - C15, 0.f);
        si += fmaxf(c.x - C10, 0.f) + fmaxf(c.y - C10, 0.f) + fmaxf(c.z - C10, 0.f) + fmaxf(c.w - C10, 0.f);
    }
    __shared__ float sred[3][8];
    __shared__ float sinv[3];
    int lane = threadIdx.x & 31, w = threadIdx.x >> 5;
    #pragma unroll
    for (int o = 16; o; o >>= 1) {
        sm += __shfl_xor_sync(0xFFFFFFFFu, sm, o);
        se += __shfl_xor_sync(0xFFFFFFFFu, se, o);
        si += __shfl_xor_sync(0xFFFFFFFFu, si, o);
    }
    if (lane == 0) { sred[0][w] = sm; sred[1][w] = se; sred[2][w] = si; }
    __syncthreads();
    if (threadIdx.x < 3) {
        float t = 0.f;
        for (int k = 0; k < (int)(blockDim.x >> 5); k++) t += sred[threadIdx.x][k];
        sinv[threadIdx.x] = 1.0f / (t + 1e-11f);
    }
    __syncthreads();
    const float im = sinv[0], ie = sinv[1], ii = sinv[2];

    __nv_bfloat162* w1 = reinterpret_cast<__nv_bfloat162*>(g_W1 + rb);
    __nv_bfloat162* w2 = reinterpret_cast<__nv_bfloat162*>(g_W2 + rb);
    for (int j = threadIdx.x; j < S2 / 4; j += blockDim.x) {
        float4 a = l4c4[j], m = mk4[j], c = lc4[j], e = we4[j];
        float o1x = e.x - a.x * (1.f - m.x) * im;
        float o1y = e.y - a.y * (1.f - m.y) * im;
        float o1z = e.z - a.z * (1.f - m.z) * im;
        float o1w = e.w - a.w * (1.f - m.w) * im;
        float o2x = fmaxf(c.x - C15, 0.f) * ie - fmaxf(c.x - C10, 0.f) * ii;
        float o2y = fmaxf(c.y - C15, 0.f) * ie - fmaxf(c.y - C10, 0.f) * ii;
        float o2z = fmaxf(c.z - C15, 0.f) * ie - fmaxf(c.z - C10, 0.f) * ii;
        float o2w = fmaxf(c.w - C15, 0.f) * ie - fmaxf(c.w - C10, 0.f) * ii;
        w1[2 * j]     = __floats2bfloat162_rn(o1x, o1y);
        w1[2 * j + 1] = __floats2bfloat162_rn(o1z, o1w);
        w2[2 * j]     = __floats2bfloat162_rn(o2x, o2y);
        w2[2 * j + 1] = __floats2bfloat162_rn(o2z, o2w);
    }
}

// ---------------- kernel 3: persistent 50-step recurrence ------------------
__device__ __forceinline__ void cp16(uint32_t saddr, const void* gptr) {
    asm volatile("cp.async.cg.shared.global [%0], [%1], 16;\n"
                 :: "r"(saddr), "l"(gptr) : "memory");
}
__device__ __forceinline__ void cp_commit() {
    asm volatile("cp.async.commit_group;\n" ::: "memory");
}
template <int N>
__device__ __forceinline__ void cp_wait() {
    asm volatile("cp.async.wait_group %0;\n" :: "n"(N) : "memory");
}

// s += dot(8 bf16 weights, 8 bf16 x) in fp32
__device__ __forceinline__ float dot8(uint4 w, uint4 x, float s) {
    float2 w0 = __bfloat1622float2(*reinterpret_cast<const __nv_bfloat162*>(&w.x));
    float2 w1 = __bfloat1622float2(*reinterpret_cast<const __nv_bfloat162*>(&w.y));
    float2 w2 = __bfloat1622float2(*reinterpret_cast<const __nv_bfloat162*>(&w.z));
    float2 w3 = __bfloat1622float2(*reinterpret_cast<const __nv_bfloat162*>(&w.w));
    float2 x0 = __bfloat1622float2(*reinterpret_cast<const __nv_bfloat162*>(&x.x));
    float2 x1 = __bfloat1622float2(*reinterpret_cast<const __nv_bfloat162*>(&x.y));
    float2 x2 = __bfloat1622float2(*reinterpret_cast<const __nv_bfloat162*>(&x.z));
    float2 x3 = __bfloat1622float2(*reinterpret_cast<const __nv_bfloat162*>(&x.w));
    s = fmaf(w0.x, x0.x, s); s = fmaf(w0.y, x0.y, s);
    s = fmaf(w1.x, x1.x, s); s = fmaf(w1.y, x1.y, s);
    s = fmaf(w2.x, x2.x, s); s = fmaf(w2.y, x2.y, s);
    s = fmaf(w3.x, x3.x, s); s = fmaf(w3.y, x3.y, s);
    return s;
}

__global__ void __launch_bounds__(1024, 1)
iterate_kernel(const float* __restrict__ thr,
               const float* __restrict__ l4thr,
               float* __restrict__ out,
               int nb) {
    extern __shared__ __nv_bfloat16 smbuf[];
    __nv_bfloat16* xl4 = smbuf;            // [S2] bf16 copy of l4 state
    __nv_bfloat16* xcu = smbuf + S2;       // [S2] bf16 copy of cur state

    const int tid  = threadIdx.x;
    const int w    = tid >> 5;
    const int lane = tid & 31;
    const int G    = gridDim.x;
    const int p    = blockIdx.x + G * w;   // row-pair index
    const bool act = (p < S2 / 2);
    const int ra   = 2 * p, rb = 2 * p + 1;

    const __nv_bfloat16 *w1a = nullptr, *w1b = nullptr, *w2a = nullptr, *w2b = nullptr;
    __nv_bfloat16* buf = nullptr;
    uint32_t bufaddr = 0;
    if (act) {
        w1a = g_W1 + (size_t)ra * S2; w1b = g_W1 + (size_t)rb * S2;
        w2a = g_W2 + (size_t)ra * S2; w2b = g_W2 + (size_t)rb * S2;
        buf = smbuf + 2 * S2 + w * (2 * 4 * CHUNK);   // 2 bufs x 4 segs x 512 bf16
        bufaddr = (uint32_t)__cvta_generic_to_shared(buf);
    }

    for (int it = 0; it < ITERS; ++it) {
        const int src = it & 1;
        const int dst = src ^ 1;

        // stage state vectors to smem as bf16 (1024 threads, 4 elems each)
        {
            float4 a = reinterpret_cast<const float4*>(g_l4[src])[tid];
            float4 b = reinterpret_cast<const float4*>(g_cur[src])[tid];
            __nv_bfloat162 a01 = __floats2bfloat162_rn(a.x, a.y);
            __nv_bfloat162 a23 = __floats2bfloat162_rn(a.z, a.w);
            __nv_bfloat162 b01 = __floats2bfloat162_rn(b.x, b.y);
            __nv_bfloat162 b23 = __floats2bfloat162_rn(b.z, b.w);
            reinterpret_cast<__nv_bfloat162*>(xl4)[2 * tid]     = a01;
            reinterpret_cast<__nv_bfloat162*>(xl4)[2 * tid + 1] = a23;
            reinterpret_cast<__nv_bfloat162*>(xcu)[2 * tid]     = b01;
            reinterpret_cast<__nv_bfloat162*>(xcu)[2 * tid + 1] = b23;
        }
        __syncthreads();

        if (act) {
            // ---- prologue: fetch chunk 0
            {
                const int base = 0;
                #pragma unroll
                for (int q = 0; q < 2; q++) {
                    const int i16 = lane + 32 * q;
                    const int gc  = i16 * 8;
                    cp16(bufaddr + (uint32_t)((base +            i16 * 8) * 2), w1a + gc);
                    cp16(bufaddr + (uint32_t)((base +  CHUNK   + i16 * 8) * 2), w1b + gc);
                    cp16(bufaddr + (uint32_t)((base + 2*CHUNK  + i16 * 8) * 2), w2a + gc);
                    cp16(bufaddr + (uint32_t)((base + 3*CHUNK  + i16 * 8) * 2), w2b + gc);
                }
                cp_commit();
            }

            float s1a = 0.f, s1b = 0.f, s2a = 0.f, s2b = 0.f;
            for (int c = 0; c < NCHUNK; ++c) {
                if (c + 1 < NCHUNK) {
                    const int base = ((c + 1) & 1) * (4 * CHUNK);
                    const int gofs = (c + 1) * CHUNK;
                    #pragma unroll
                    for (int q = 0; q < 2; q++) {
                        const int i16 = lane + 32 * q;
                        const int gc  = gofs + i16 * 8;
                        cp16(bufaddr + (uint32_t)((base +           i16 * 8) * 2), w1a + gc);
                        cp16(bufaddr + (uint32_t)((base + CHUNK   + i16 * 8) * 2), w1b + gc);
                        cp16(bufaddr + (uint32_t)((base + 2*CHUNK + i16 * 8) * 2), w2a + gc);
                        cp16(bufaddr + (uint32_t)((base + 3*CHUNK + i16 * 8) * 2), w2b + gc);
                    }
                    cp_commit();
                    cp_wait<1>();
                } else {
                    cp_wait<0>();
                }
                const int base = (c & 1) * (4 * CHUNK);
                #pragma unroll
                for (int q = 0; q < 2; q++) {
                    const int i16 = lane + 32 * q;
                    const int col = c * CHUNK + i16 * 8;
                    uint4 xv1 = *reinterpret_cast<const uint4*>(xl4 + col);
                    uint4 xv2 = *reinterpret_cast<const uint4*>(xcu + col);
                    uint4 a1  = *reinterpret_cast<const uint4*>(buf + base +             i16 * 8);
                    uint4 b1  = *reinterpret_cast<const uint4*>(buf + base + CHUNK     + i16 * 8);
                    uint4 a2  = *reinterpret_cast<const uint4*>(buf + base + 2 * CHUNK + i16 * 8);
                    uint4 b2  = *reinterpret_cast<const uint4*>(buf + base + 3 * CHUNK + i16 * 8);
                    s1a = dot8(a1, xv1, s1a);
                    s1b = dot8(b1, xv1, s1b);
                    s2a = dot8(a2, xv2, s2a);
                    s2b = dot8(b2, xv2, s2b);
                }
            }
            #pragma unroll
            for (int o = 16; o; o >>= 1) {
                s1a += __shfl_xor_sync(0xFFFFFFFFu, s1a, o);
                s1b += __shfl_xor_sync(0xFFFFFFFFu, s1b, o);
                s2a += __shfl_xor_sync(0xFFFFFFFFu, s2a, o);
                s2b += __shfl_xor_sync(0xFFFFFFFFu, s2b, o);
            }
            if (lane < 2) {
                const int   r  = (lane == 0) ? ra : rb;
                const float s1 = (lane == 0) ? s1a : s1b;
                const float s2 = (lane == 0) ? s2a : s2b;
                // b*0.5 == 0.5f exactly in fp32
                float l4a  = g_aff[r] * 0.5f + g_cur[src][r] * 0.5f;
                float l4n  = tanhf(fmaxf(l4a + s1 - l4thr[r], 0.f) * 2.0f);
                float curn = tanhf(fmaxf(l4n + s2 - thr[r], 0.f));
                g_l4[dst][r]  = l4n;
                g_cur[dst][r] = curn;
                if (it == ITERS - 1) out[r] = curn;
            }
        }

        // ---- grid barrier (sense-reversing; grid == #SMs, all co-resident)
        __syncthreads();
        if (tid == 0) {
            __threadfence();
            unsigned gen = g_bargen;
            if (atomicAdd(&g_barcnt, 1u) == (unsigned)nb - 1u) {
                g_barcnt = 0;
                __threadfence();
                g_bargen = gen + 1u;
            } else {
                while (g_bargen == gen) { __nanosleep(32); }
            }
            __threadfence();
        }
        __syncthreads();
    }
}

// ---------------------------------------------------------------------------
extern "C" void kernel_launch(void* const* d_in, const int* in_sizes, int n_in,
                              void* d_out, int out_size) {
    const float* input_crop = (const float*)d_in[0];
    const int*   rf_grids   = (const int*)  d_in[1];
    const float* aff_w      = (const float*)d_in[2];
    const float* lc         = (const float*)d_in[3];
    const float* l4c        = (const float*)d_in[4];
    const float* lwe        = (const float*)d_in[5];
    const float* masks      = (const float*)d_in[6];
    const float* thr        = (const float*)d_in[7];
    const float* l4thr      = (const float*)d_in[8];
    float* out = (float*)d_out;

    int dev = 0;
    cudaGetDevice(&dev);
    int sms = 0;
    cudaDeviceGetAttribute(&sms, cudaDevAttrMultiProcessorCount, dev);
    if (sms < 128) sms = 148;   // B200: 148 SMs; row-pair mapping needs G >= 128

    // dynamic smem: 2*S2 (state bf16) + NWSLOT warps * 2 bufs * 4 segs * CHUNK bf16
    const int smem_bytes = (2 * S2 + NWSLOT * 2 * 4 * CHUNK) * (int)sizeof(__nv_bfloat16);
    cudaFuncSetAttribute(iterate_kernel,
                         cudaFuncAttributeMaxDynamicSharedMemorySize, smem_bytes);

    aff_init_kernel<<<512, 256>>>(input_crop, rf_grids, aff_w);
    build_w_kernel<<<S2, 256>>>(lc, l4c, lwe, masks);
    iterate_kernel<<<sms, 1024, smem_bytes>>>(thr, l4thr, out, sms);
}

// round 4
// speedup vs baseline: 6.4097x; 1.1410x over previous
#include <cuda_runtime.h>
#include <cuda_bf16.h>
#include <cstdint>

#define S2     4096
#define NPATCH 225
#define INPUT  48
#define ITERS  50
#define CHUNK  1024                // columns per W2 pipeline chunk
#define NCHUNK (S2 / CHUNK)        // 4
#define NWSLOT 16                  // warp buffer slots (covers grid >= 128)
#define WIN_DY 33                  // dy in [-16, 16]
#define WIN_W  40                  // 8-aligned x window, covers x +/- 16
#define WIN_N  (WIN_DY * WIN_W)    // 1320 entries per unit

// ---------------- scratch (device globals: allocation-free) ----------------
__device__ __align__(16) __nv_bfloat16 g_W2[(size_t)S2 * S2];     // exc_n - inh_n
__device__ __align__(16) __nv_bfloat16 g_W1win[(size_t)S2 * WIN_N]; // windowed l4_w
__device__ float g_aff[S2];
__device__ __align__(16) __nv_bfloat16 g_xl4[2][S2];              // bf16 state (matvec input)
__device__ __align__(16) __nv_bfloat16 g_xcu[2][S2];
__device__ unsigned g_barcnt = 0;
__device__ volatile unsigned g_bargen = 0;

// ---------------- kernel 1: afferent drive + state init --------------------
__global__ void aff_init_kernel(const float* __restrict__ img,
                                const int*   __restrict__ rfg,
                                const float* __restrict__ aw) {
    int gtid = blockIdx.x * blockDim.x + threadIdx.x;
    if (gtid < S2) {
        g_xl4[0][gtid] = __float2bfloat16(0.f);
        g_xl4[1][gtid] = __float2bfloat16(0.f);
        g_xcu[0][gtid] = __float2bfloat16(0.f);
        g_xcu[1][gtid] = __float2bfloat16(0.f);
    }
    int u    = gtid >> 5;
    int lane = gtid & 31;
    if (u >= S2) return;
    const int*   rg = rfg + (size_t)u * NPATCH * 2;
    const float* ww = aw  + (size_t)u * NPATCH;
    float s = 0.f;
    for (int i = lane; i < NPATCH; i += 32) {
        int g0 = rg[2 * i];
        int g1 = rg[2 * i + 1];
        s += img[g0 * INPUT + g1] * ww[i];
    }
    #pragma unroll
    for (int o = 16; o; o >>= 1) s += __shfl_xor_sync(0xFFFFFFFFu, s, o);
    if (lane == 0) g_aff[u] = s;
}

// ---------------- kernel 2a: dense W2 = exc_n - inh_n (bf16) ---------------
__global__ void build_w2_kernel(const float* __restrict__ lc) {
    const int i = blockIdx.x;
    const size_t rb = (size_t)i * S2;
    const float4* lc4 = reinterpret_cast<const float4*>(lc + rb);
    const float C15 = 1.5f / 4096.0f;
    const float C10 = 1.0f / 4096.0f;

    float se = 0.f, si = 0.f;
    for (int j = threadIdx.x; j < S2 / 4; j += blockDim.x) {
        float4 c = lc4[j];
        se += fmaxf(c.x - C15, 0.f) + fmaxf(c.y - C15, 0.f) + fmaxf(c.z - C15, 0.f) + fmaxf(c.w - C15, 0.f);
        si += fmaxf(c.x - C10, 0.f) + fmaxf(c.y - C10, 0.f) + fmaxf(c.z - C10, 0.f) + fmaxf(c.w - C10, 0.f);
    }
    __shared__ float sred[2][8];
    __shared__ float sinv[2];
    int lane = threadIdx.x & 31, w = threadIdx.x >> 5;
    #pragma unroll
    for (int o = 16; o; o >>= 1) {
        se += __shfl_xor_sync(0xFFFFFFFFu, se, o);
        si += __shfl_xor_sync(0xFFFFFFFFu, si, o);
    }
    if (lane == 0) { sred[0][w] = se; sred[1][w] = si; }
    __syncthreads();
    if (threadIdx.x < 2) {
        float t = 0.f;
        for (int k = 0; k < (int)(blockDim.x >> 5); k++) t += sred[threadIdx.x][k];
        sinv[threadIdx.x] = 1.0f / (t + 1e-11f);
    }
    __syncthreads();
    const float ie = sinv[0], ii = sinv[1];

    __nv_bfloat162* w2 = reinterpret_cast<__nv_bfloat162*>(g_W2 + rb);
    for (int j = threadIdx.x; j < S2 / 4; j += blockDim.x) {
        float4 c = lc4[j];
        float ox = fmaxf(c.x - C15, 0.f) * ie - fmaxf(c.x - C10, 0.f) * ii;
        float oy = fmaxf(c.y - C15, 0.f) * ie - fmaxf(c.y - C10, 0.f) * ii;
        float oz = fmaxf(c.z - C15, 0.f) * ie - fmaxf(c.z - C10, 0.f) * ii;
        float ow = fmaxf(c.w - C15, 0.f) * ie - fmaxf(c.w - C10, 0.f) * ii;
        w2[2 * j]     = __floats2bfloat162_rn(ox, oy);
        w2[2 * j + 1] = __floats2bfloat162_rn(oz, ow);
    }
}

// ---------------- kernel 2b: windowed W1 (lwe - mid_norm), bf16 ------------
// One block per sheet unit. mid's support (dist<=12.5) and lwe's non-negligible
// support (dist<=16, truncated mass ~1e-9) lie inside the 33x40 window.
__global__ void build_w1win_kernel(const float* __restrict__ l4c,
                                   const float* __restrict__ lwe,
                                   const float* __restrict__ masks) {
    const int i = blockIdx.x;
    const int y = i >> 6, x = i & 63;
    int xs = (x - 16) & ~7;
    if (xs < 0) xs = 0;
    if (xs > 24) xs = 24;
    const size_t rb = (size_t)i * S2;

    // pass 1: mid row-sum over window (== full-row sum, support inside window)
    float s = 0.f;
    for (int e = threadIdx.x; e < WIN_N; e += blockDim.x) {
        int dyi = e / WIN_W, k = e - WIN_W * dyi;
        int jy = y - 16 + dyi;
        if (jy >= 0 && jy < 64) {
            int j = jy * 64 + xs + k;
            s += l4c[rb + j] * (1.f - masks[rb + j]);
        }
    }
    __shared__ float sred[8];
    __shared__ float sinv;
    int lane = threadIdx.x & 31, w = threadIdx.x >> 5;
    #pragma unroll
    for (int o = 16; o; o >>= 1) s += __shfl_xor_sync(0xFFFFFFFFu, s, o);
    if (lane == 0) sred[w] = s;
    __syncthreads();
    if (threadIdx.x == 0) {
        float t = 0.f;
        for (int k = 0; k < (int)(blockDim.x >> 5); k++) t += sred[k];
        sinv = 1.0f / (t + 1e-11f);
    }
    __syncthreads();
    const float inv = sinv;

    // pass 2: write window
    __nv_bfloat16* dst = g_W1win + (size_t)i * WIN_N;
    for (int e = threadIdx.x; e < WIN_N; e += blockDim.x) {
        int dyi = e / WIN_W, k = e - WIN_W * dyi;
        int jy = y - 16 + dyi;
        float v = 0.f;
        if (jy >= 0 && jy < 64) {
            int j = jy * 64 + xs + k;
            v = lwe[rb + j] - l4c[rb + j] * (1.f - masks[rb + j]) * inv;
        }
        dst[e] = __float2bfloat16(v);
    }
}

// ---------------- kernel 3: persistent 50-step recurrence ------------------
__device__ __forceinline__ void cp16(uint32_t saddr, const void* gptr) {
    asm volatile("cp.async.cg.shared.global [%0], [%1], 16;\n"
                 :: "r"(saddr), "l"(gptr) : "memory");
}
__device__ __forceinline__ void cp_commit() {
    asm volatile("cp.async.commit_group;\n" ::: "memory");
}
template <int N>
__device__ __forceinline__ void cp_wait() {
    asm volatile("cp.async.wait_group %0;\n" :: "n"(N) : "memory");
}

// fp32 dot of 8 bf16 weights with 8 bf16 x
__device__ __forceinline__ float dot8(uint4 w, uint4 x, float s) {
    float2 w0 = __bfloat1622float2(*reinterpret_cast<const __nv_bfloat162*>(&w.x));
    float2 w1 = __bfloat1622float2(*reinterpret_cast<const __nv_bfloat162*>(&w.y));
    float2 w2 = __bfloat1622float2(*reinterpret_cast<const __nv_bfloat162*>(&w.z));
    float2 w3 = __bfloat1622float2(*reinterpret_cast<const __nv_bfloat162*>(&w.w));
    float2 x0 = __bfloat1622float2(*reinterpret_cast<const __nv_bfloat162*>(&x.x));
    float2 x1 = __bfloat1622float2(*reinterpret_cast<const __nv_bfloat162*>(&x.y));
    float2 x2 = __bfloat1622float2(*reinterpret_cast<const __nv_bfloat162*>(&x.z));
    float2 x3 = __bfloat1622float2(*reinterpret_cast<const __nv_bfloat162*>(&x.w));
    s = fmaf(w0.x, x0.x, s); s = fmaf(w0.y, x0.y, s);
    s = fmaf(w1.x, x1.x, s); s = fmaf(w1.y, x1.y, s);
    s = fmaf(w2.x, x2.x, s); s = fmaf(w2.y, x2.y, s);
    s = fmaf(w3.x, x3.x, s); s = fmaf(w3.y, x3.y, s);
    return s;
}

__global__ void __launch_bounds__(1024, 1)
iterate_kernel(const float* __restrict__ thr,
               const float* __restrict__ l4thr,
               float* __restrict__ out,
               int nb) {
    extern __shared__ __nv_bfloat16 smbuf[];
    __nv_bfloat16* xl4 = smbuf;            // [S2] bf16 l4 state
    __nv_bfloat16* xcu = smbuf + S2;       // [S2] bf16 cur state

    const int tid  = threadIdx.x;
    const int w    = tid >> 5;
    const int lane = tid & 31;
    const int G    = gridDim.x;
    const int p    = blockIdx.x + G * w;   // row-pair index
    const bool act = (p < S2 / 2);
    const int ra   = 2 * p, rbr = 2 * p + 1;

    // per-row loop-invariant scalars + pointers
    const __nv_bfloat16 *w2a = nullptr, *w2b = nullptr, *wina = nullptr, *winb = nullptr;
    __nv_bfloat16* buf = nullptr;
    uint32_t bufaddr = 0;
    int basea = 0, baseb = 0;              // clamped smem x-row base for stencil
    float aff_a = 0.f, aff_b = 0.f, thr_a = 0.f, thr_b = 0.f, l4t_a = 0.f, l4t_b = 0.f;
    if (act) {
        w2a  = g_W2 + (size_t)ra * S2;
        w2b  = g_W2 + (size_t)rbr * S2;
        wina = g_W1win + (size_t)ra * WIN_N;
        winb = g_W1win + (size_t)rbr * WIN_N;
        buf = smbuf + 2 * S2 + w * (2 * 2 * CHUNK);
        bufaddr = (uint32_t)__cvta_generic_to_shared(buf);
        int ya = ra >> 6, xa = ra & 63;
        int yb = rbr >> 6, xb = rbr & 63;
        int xsa = (xa - 16) & ~7; if (xsa < 0) xsa = 0; if (xsa > 24) xsa = 24;
        int xsb = (xb - 16) & ~7; if (xsb < 0) xsb = 0; if (xsb > 24) xsb = 24;
        basea = (ya - 16) * 64 + xsa;      // + dyi*64 later; clamp per-task
        baseb = (yb - 16) * 64 + xsb;
        aff_a = g_aff[ra]; aff_b = g_aff[rbr];
        thr_a = thr[ra];   thr_b = thr[rbr];
        l4t_a = l4thr[ra]; l4t_b = l4thr[rbr];
    }
    float cur_a = 0.f, cur_b = 0.f;        // exact fp32 recurrent state (per warp)

    for (int it = 0; it < ITERS; ++it) {
        const int src = it & 1;
        const int dst = src ^ 1;

        // prologue: prefetch W2 chunk 0 (independent of state)
        if (act) {
            #pragma unroll
            for (int q = 0; q < 4; q++) {
                const int i16 = lane + 32 * q;
                cp16(bufaddr + (uint32_t)((i16 * 8) * 2),           w2a + i16 * 8);
                cp16(bufaddr + (uint32_t)((CHUNK + i16 * 8) * 2),   w2b + i16 * 8);
            }
            cp_commit();
        }

        // stage bf16 state vectors (8 B per thread per vector)
        reinterpret_cast<uint2*>(xl4)[tid] = reinterpret_cast<const uint2*>(g_xl4[src])[tid];
        reinterpret_cast<uint2*>(xcu)[tid] = reinterpret_cast<const uint2*>(g_xcu[src])[tid];
        __syncthreads();

        if (act) {
            // ---- W1 stencil (windowed): 2 rows x 165 uint4 tasks ----
            float s1a = 0.f, s1b = 0.f;
            for (int t = lane; t < 330; t += 32) {
                const bool isB = (t >= 165);
                const int  tt  = isB ? t - 165 : t;
                const int  dyi = tt / 5;
                const int  xoff = (isB ? baseb : basea) + dyi * 64 - dyi * 64 + 0; // placeholder
                int xi = (isB ? baseb : basea) + dyi * 64 + (tt - 5 * dyi) * 8;
                if (xi < 0) xi = 0;
                if (xi > S2 - 8) xi = S2 - 8;        // weights are 0 there anyway
                const __nv_bfloat16* win = isB ? winb : wina;
                uint4 wv = *reinterpret_cast<const uint4*>(win + tt * 8);
                uint4 xv = *reinterpret_cast<const uint4*>(xl4 + xi);
                float acc = dot8(wv, xv, 0.f);
                if (isB) s1b += acc; else s1a += acc;
                (void)xoff;
            }

            // ---- W2 dense matvec, cp.async double-buffered ----
            float s2a = 0.f, s2b = 0.f;
            for (int c = 0; c < NCHUNK; ++c) {
                if (c + 1 < NCHUNK) {
                    const int base = ((c + 1) & 1) * (2 * CHUNK);
                    const int gofs = (c + 1) * CHUNK;
                    #pragma unroll
                    for (int q = 0; q < 4; q++) {
                        const int i16 = lane + 32 * q;
                        cp16(bufaddr + (uint32_t)((base +         i16 * 8) * 2), w2a + gofs + i16 * 8);
                        cp16(bufaddr + (uint32_t)((base + CHUNK + i16 * 8) * 2), w2b + gofs + i16 * 8);
                    }
                    cp_commit();
                    cp_wait<1>();
                } else {
                    cp_wait<0>();
                }
                const int base = (c & 1) * (2 * CHUNK);
                #pragma unroll
                for (int q = 0; q < 4; q++) {
                    const int i16 = lane + 32 * q;
                    const int col = c * CHUNK + i16 * 8;
                    uint4 xv = *reinterpret_cast<const uint4*>(xcu + col);
                    uint4 a2 = *reinterpret_cast<const uint4*>(buf + base +         i16 * 8);
                    uint4 b2 = *reinterpret_cast<const uint4*>(buf + base + CHUNK + i16 * 8);
                    s2a = dot8(a2, xv, s2a);
                    s2b = dot8(b2, xv, s2b);
                }
            }

            // ---- reduce + pointwise update (redundant across lanes; cheap) ----
            #pragma unroll
            for (int o = 16; o; o >>= 1) {
                s1a += __shfl_xor_sync(0xFFFFFFFFu, s1a, o);
                s1b += __shfl_xor_sync(0xFFFFFFFFu, s1b, o);
                s2a += __shfl_xor_sync(0xFFFFFFFFu, s2a, o);
                s2b += __shfl_xor_sync(0xFFFFFFFFu, s2b, o);
            }
            // b*0.5 == 0.5f exactly in fp32
            float l4n_a = tanhf(fmaxf(aff_a * 0.5f + cur_a * 0.5f + s1a - l4t_a, 0.f) * 2.0f);
            float l4n_b = tanhf(fmaxf(aff_b * 0.5f + cur_b * 0.5f + s1b - l4t_b, 0.f) * 2.0f);
            float cn_a  = tanhf(fmaxf(l4n_a + s2a - thr_a, 0.f));
            float cn_b  = tanhf(fmaxf(l4n_b + s2b - thr_b, 0.f));
            cur_a = cn_a; cur_b = cn_b;
            if (lane == 0) {
                g_xl4[dst][ra] = __float2bfloat16(l4n_a);
                g_xcu[dst][ra] = __float2bfloat16(cn_a);
                if (it == ITERS - 1) out[ra] = cn_a;
            }
            if (lane == 1) {
                g_xl4[dst][rbr] = __float2bfloat16(l4n_b);
                g_xcu[dst][rbr] = __float2bfloat16(cn_b);
                if (it == ITERS - 1) out[rbr] = cn_b;
            }
        }

        // ---- grid barrier (sense-reversing; grid == #SMs, all co-resident)
        __syncthreads();
        if (tid == 0) {
            __threadfence();
            unsigned gen = g_bargen;
            if (atomicAdd(&g_barcnt, 1u) == (unsigned)nb - 1u) {
                g_barcnt = 0;
                __threadfence();
                g_bargen = gen + 1u;
            } else {
                while (g_bargen == gen) { __nanosleep(32); }
            }
            __threadfence();
        }
        __syncthreads();
    }
}

// ---------------------------------------------------------------------------
extern "C" void kernel_launch(void* const* d_in, const int* in_sizes, int n_in,
                              void* d_out, int out_size) {
    const float* input_crop = (const float*)d_in[0];
    const int*   rf_grids   = (const int*)  d_in[1];
    const float* aff_w      = (const float*)d_in[2];
    const float* lc         = (const float*)d_in[3];
    const float* l4c        = (const float*)d_in[4];
    const float* lwe        = (const float*)d_in[5];
    const float* masks      = (const float*)d_in[6];
    const float* thr        = (const float*)d_in[7];
    const float* l4thr      = (const float*)d_in[8];
    float* out = (float*)d_out;

    int dev = 0;
    cudaGetDevice(&dev);
    int sms = 0;
    cudaDeviceGetAttribute(&sms, cudaDevAttrMultiProcessorCount, dev);
    if (sms < 128) sms = 148;   // B200: 148 SMs; row-pair mapping needs G >= 128

    // dynamic smem: 2*S2 state + NWSLOT warps * (2 bufs * 2 segs * CHUNK) bf16
    const int smem_bytes = (2 * S2 + NWSLOT * 2 * 2 * CHUNK) * (int)sizeof(__nv_bfloat16);
    cudaFuncSetAttribute(iterate_kernel,
                         cudaFuncAttributeMaxDynamicSharedMemorySize, smem_bytes);

    aff_init_kernel<<<512, 256>>>(input_crop, rf_grids, aff_w);
    build_w2_kernel<<<S2, 256>>>(lc);
    build_w1win_kernel<<<S2, 128>>>(l4c, lwe, masks);
    iterate_kernel<<<sms, 1024, smem_bytes>>>(thr, l4thr, out, sms);
}